// round 1
// baseline (speedup 1.0000x reference)
#include <cuda_runtime.h>

#define ROWS 4096
#define COLS 6144
#define VEC_PER_ROW (COLS / 4)      // 1536 float4 per row
#define PHI_VEC     (4096 / 4)      // 1024 float4 cover cols [0,4096)
#define THREADS 256

// Per-row partial sums (scratch; no allocation allowed in kernel_launch).
__device__ float g_rt[ROWS];    // r-sum if row%3==0, theta-sum if row%3==1, 0 if row%3==2
__device__ float g_phi[ROWS];   // phi-sum for every row

__device__ __forceinline__ float sigmoidf(float x) {
    // 2 MUFU (EX2 + RCP) + 1 FMA; ~1e-7 rel err, far below 1e-3 tolerance.
    return __fdividef(1.0f, 1.0f + __expf(-x));
}

__global__ void __launch_bounds__(THREADS)
spherical_pass1(const float* __restrict__ preds, const float* __restrict__ targs) {
    const int r = blockIdx.x;
    const int rowmod = r % 3;
    const float4* __restrict__ p4 = (const float4*)(preds + (size_t)r * COLS);
    const float4* __restrict__ t4 = (const float4*)(targs + (size_t)r * COLS);

    // rows ==2 mod 3 contribute only phi, which lives in cols [0,4096)
    const int nvec = (rowmod == 2) ? PHI_VEC : VEC_PER_ROW;

    float srt = 0.0f;   // r or theta partial
    float sphi = 0.0f;  // phi partial

    for (int i = threadIdx.x; i < nvec; i += THREADS) {
        float4 p = p4[i];
        float4 t = t4[i];
        const int c0 = 4 * i;
        float pv[4] = {p.x, p.y, p.z, p.w};
        float tv[4] = {t.x, t.y, t.z, t.w};
#pragma unroll
        for (int j = 0; j < 4; j++) {
            const int c = c0 + j;
            float s  = sigmoidf(pv[j]);
            float ad = fabsf(s - tv[j]);
            if (rowmod < 2) srt += ad;
            if (c < 4096 && (c % 3) == 2) sphi += fminf(ad, 1.0f - ad);
        }
    }

    // Deterministic block reduction (warp shuffle tree + shared)
    __shared__ float sh_rt[THREADS / 32];
    __shared__ float sh_phi[THREADS / 32];
#pragma unroll
    for (int o = 16; o > 0; o >>= 1) {
        srt  += __shfl_down_sync(0xFFFFFFFFu, srt,  o);
        sphi += __shfl_down_sync(0xFFFFFFFFu, sphi, o);
    }
    const int lane = threadIdx.x & 31;
    const int warp = threadIdx.x >> 5;
    if (lane == 0) { sh_rt[warp] = srt; sh_phi[warp] = sphi; }
    __syncthreads();
    if (warp == 0) {
        srt  = (lane < THREADS / 32) ? sh_rt[lane]  : 0.0f;
        sphi = (lane < THREADS / 32) ? sh_phi[lane] : 0.0f;
#pragma unroll
        for (int o = 4; o > 0; o >>= 1) {
            srt  += __shfl_down_sync(0xFFFFFFFFu, srt,  o);
            sphi += __shfl_down_sync(0xFFFFFFFFu, sphi, o);
        }
        if (lane == 0) { g_rt[r] = srt; g_phi[r] = sphi; }
    }
}

#define FIN_THREADS 1024

__global__ void __launch_bounds__(FIN_THREADS)
spherical_pass2(float* __restrict__ out) {
    float rs = 0.0f, ts = 0.0f, ps = 0.0f;
    for (int i = threadIdx.x; i < ROWS; i += FIN_THREADS) {
        float v = g_rt[i];
        int m = i % 3;
        if (m == 0)      rs += v;
        else if (m == 1) ts += v;
        ps += g_phi[i];
    }
    __shared__ float sh[3][FIN_THREADS / 32];
#pragma unroll
    for (int o = 16; o > 0; o >>= 1) {
        rs += __shfl_down_sync(0xFFFFFFFFu, rs, o);
        ts += __shfl_down_sync(0xFFFFFFFFu, ts, o);
        ps += __shfl_down_sync(0xFFFFFFFFu, ps, o);
    }
    const int lane = threadIdx.x & 31;
    const int warp = threadIdx.x >> 5;
    if (lane == 0) { sh[0][warp] = rs; sh[1][warp] = ts; sh[2][warp] = ps; }
    __syncthreads();
    if (warp == 0) {
        rs = (lane < FIN_THREADS / 32) ? sh[0][lane] : 0.0f;
        ts = (lane < FIN_THREADS / 32) ? sh[1][lane] : 0.0f;
        ps = (lane < FIN_THREADS / 32) ? sh[2][lane] : 0.0f;
#pragma unroll
        for (int o = 16; o > 0; o >>= 1) {
            rs += __shfl_down_sync(0xFFFFFFFFu, rs, o);
            ts += __shfl_down_sync(0xFFFFFFFFu, ts, o);
            ps += __shfl_down_sync(0xFFFFFFFFu, ps, o);
        }
        if (lane == 0) {
            // counts: rows 0::3 -> 1366 rows, rows 1::3 -> 1365 rows,
            // phi denominator is b * n_vecs = 4096 * (6144/3) = 4096*2048 (per reference)
            float r_loss   = rs / (1366.0f * 6144.0f);
            float t_loss   = ts / (1365.0f * 6144.0f);
            float phi_loss = ps / (4096.0f * 2048.0f);
            out[0] = r_loss + t_loss + phi_loss;
            out[1] = r_loss;
            out[2] = t_loss;
            out[3] = phi_loss;
        }
    }
}

extern "C" void kernel_launch(void* const* d_in, const int* in_sizes, int n_in,
                              void* d_out, int out_size) {
    const float* preds = (const float*)d_in[0];
    const float* targs = (const float*)d_in[1];
    float* out = (float*)d_out;
    (void)in_sizes; (void)n_in; (void)out_size;

    spherical_pass1<<<ROWS, THREADS>>>(preds, targs);
    spherical_pass2<<<1, FIN_THREADS>>>(out);
}